// round 16
// baseline (speedup 1.0000x reference)
#include <cuda_runtime.h>
#include <math.h>

#define H 2048
#define V 50257
#define L 20

// Programmatic dependent launch controls (sm_90+)
#define GDC_LAUNCH() asm volatile("griddepcontrol.launch_dependents;")
#define GDC_WAIT()   asm volatile("griddepcontrol.wait;" ::: "memory")

// Scratch (device globals: no allocation allowed in kernel_launch)
__device__ __align__(16) float g_sc[L];           // raw attention scores
__device__ __align__(16) float g_concat[2 * H];   // [embedded ; context]
__device__ __align__(16) float g_x[H];            // relu(comb) output
__device__ __align__(16) float g_gh[3 * H];       // w_hh @ h0 + b_hh
__device__ __align__(16) float g_hnew[H];         // new hidden

// Self-resetting sync counters for k1 (return to 0 by end of each launch).
__device__ int c_sc  = 0;     // score blocks done (target 20)
__device__ int c_fin = 0;     // ctx blocks finished (target 8; last one resets)

__device__ __forceinline__ float warp_reduce(float v) {
    #pragma unroll
    for (int o = 16; o > 0; o >>= 1)
        v += __shfl_xor_sync(0xFFFFFFFFu, v, o);
    return v;
}

__device__ __forceinline__ float dot4(float4 a, float4 b) {
    return a.x * b.x + a.y * b.y + a.z * b.z + a.w * b.w;
}

// ---------------------------------------------------------------------------
// K1: fused attention. Blocks 0..19: one score each. Blocks 20..27: softmax
// (redundant) + context + concat (256 j's each), spin on score counter.
// All blocks GDC_LAUNCH at entry -> k2's gh stream starts at k1's START.
// ---------------------------------------------------------------------------
__global__ void __launch_bounds__(256) k1_fused(
    const int* __restrict__ input_ids,
    const float* __restrict__ hidden,
    const float* __restrict__ emb,
    const float* __restrict__ attn_w,
    const float* __restrict__ attn_b,
    const float* __restrict__ enc,
    float* __restrict__ out)
{
    GDC_LAUNCH();
    const int bid = blockIdx.x;
    const int tid = threadIdx.x;
    const int id  = input_ids[0];

    if (bid < L) {
        // ---- score block: s[bid] = attn_w[bid] . [emb_row ; h0] + b ----
        __shared__ float red[8];
        const float4* aw = reinterpret_cast<const float4*>(attn_w + bid * (2 * H));
        const float4* e4 = reinterpret_cast<const float4*>(emb + (long long)id * H);
        const float4* h4 = reinterpret_cast<const float4*>(hidden);

        float s = 0.f;
        #pragma unroll
        for (int i = tid; i < 1024; i += 256) {
            float4 a = __ldcs(aw + i);
            float4 x = (i < 512) ? e4[i] : h4[i - 512];
            s += dot4(a, x);
        }
        s = warp_reduce(s);
        if ((tid & 31) == 0) red[tid >> 5] = s;
        __syncthreads();
        if (tid < 8) {
            float v = red[tid];
            #pragma unroll
            for (int o = 4; o > 0; o >>= 1) v += __shfl_xor_sync(0xFFu, v, o);
            if (tid == 0) {
                g_sc[bid] = v + attn_b[bid];
                __threadfence();
                atomicAdd(&c_sc, 1);
            }
        }
    } else {
        // ---- ctx block: wait for all 20 scores, then context + concat ----
        __shared__ float sw[L];
        if (tid == 0) {
            while (atomicAdd(&c_sc, 0) < L) __nanosleep(64);
        }
        __syncthreads();
        __threadfence();

        if (tid == 0) {
            float m = g_sc[0];
            #pragma unroll
            for (int l = 1; l < L; l++) m = fmaxf(m, g_sc[l]);
            float ssum = 0.f;
            float e[L];
            #pragma unroll
            for (int l = 0; l < L; l++) { e[l] = __expf(g_sc[l] - m); ssum += e[l]; }
            float inv = 1.f / ssum;
            #pragma unroll
            for (int l = 0; l < L; l++) sw[l] = e[l] * inv;
        }
        __syncthreads();

        const int j = (bid - L) * 256 + tid;      // 0..2047
        float ctx = 0.f;
        #pragma unroll
        for (int l = 0; l < L; l++)
            ctx += sw[l] * enc[l * H + j];

        g_concat[j]     = emb[(long long)id * H + j];
        g_concat[H + j] = ctx;

        if (bid == L && tid < L) out[V + H + tid] = sw[tid];

        __syncthreads();
        if (tid == 0) {
            int f = atomicAdd(&c_fin, 1);
            if (f == 7) {                          // last ctx block: reset
                atomicExch(&c_sc, 0);
                atomicExch(&c_fin, 0);
            }
        }
    }
}

// ---------------------------------------------------------------------------
// K2: gh GEMV in blocks 0..767 (NO dependency -> streams from k1's start),
//     comb GEMV in blocks 768..1023 (prefetch QUARTER row = 8 float4 to
//     keep whole-kernel regs ~60 and gh occupancy high, then wait on k1).
// ---------------------------------------------------------------------------
__global__ void __launch_bounds__(256) k2_comb_gh(
    const float* __restrict__ comb_w, const float* __restrict__ comb_b,
    const float* __restrict__ w_hh,   const float* __restrict__ b_hh,
    const float* __restrict__ hidden)
{
    GDC_LAUNCH();
    __shared__ float4 xs[1024];
    const int tid  = threadIdx.x;
    const int warp = tid >> 5;
    const int lane = tid & 31;

    if (blockIdx.x < 768) {
        for (int i = tid; i < 512; i += 256)
            xs[i] = reinterpret_cast<const float4*>(hidden)[i];
        __syncthreads();

        const int r = blockIdx.x * 8 + warp;              // 0..6143
        const float4* w = reinterpret_cast<const float4*>(w_hh) + (long long)r * 512;
        float s = 0.f;
        #pragma unroll 8
        for (int i = lane; i < 512; i += 32)
            s += dot4(__ldcs(w + i), xs[i]);
        s = warp_reduce(s);
        if (lane == 0) g_gh[r] = s + b_hh[r];
    } else {
        const int r = (blockIdx.x - 768) * 8 + warp;      // 0..2047
        const float4* w = reinterpret_cast<const float4*>(comb_w) + (long long)r * 1024;

        float4 wreg[8];
        #pragma unroll
        for (int j = 0; j < 8; j++)
            wreg[j] = __ldcs(w + lane + 32 * j);          // i in [0, 256)

        GDC_WAIT();                                       // g_concat from k1
        for (int i = tid; i < 1024; i += 256)
            xs[i] = reinterpret_cast<const float4*>(g_concat)[i];
        __syncthreads();

        float s = 0.f;
        #pragma unroll
        for (int j = 0; j < 8; j++)
            s += dot4(wreg[j], xs[lane + 32 * j]);
        #pragma unroll 8
        for (int i = 256 + lane; i < 1024; i += 32)
            s += dot4(__ldcs(w + i), xs[i]);
        s = warp_reduce(s);
        if (lane == 0) g_x[r] = fmaxf(s + comb_b[r], 0.f);
    }
}

// ---------------------------------------------------------------------------
// K3: gi GEMV + GRU gates. block = 384 (12 warps = 4 k's x 3 gates),
// grid = 512. Half-row prefetch (8 float4) before the wait.
// ---------------------------------------------------------------------------
__global__ void __launch_bounds__(384) k3_gru(
    const float* __restrict__ w_ih, const float* __restrict__ b_ih,
    const float* __restrict__ hidden, float* __restrict__ out)
{
    GDC_LAUNCH();
    __shared__ float4 xs[512];
    __shared__ float s_gi[4][3];
    const int tid  = threadIdx.x;
    const int warp = tid >> 5;
    const int lane = tid & 31;

    const int kl   = warp / 3;            // 0..3
    const int gate = warp - kl * 3;       // 0..2
    const int k    = blockIdx.x * 4 + kl;
    const int row  = k + gate * H;

    const float4* w = reinterpret_cast<const float4*>(w_ih) + (long long)row * 512;
    float4 wreg[8];
    #pragma unroll
    for (int j = 0; j < 8; j++)
        wreg[j] = __ldcs(w + lane + 32 * j);  // first half of the row

    GDC_WAIT();                           // g_x + g_gh from k2
    for (int i = tid; i < 512; i += 384)
        xs[i] = reinterpret_cast<const float4*>(g_x)[i];
    __syncthreads();

    float s = 0.f;
    #pragma unroll
    for (int j = 0; j < 8; j++)
        s += dot4(wreg[j], xs[lane + 32 * j]);
    #pragma unroll 8
    for (int i = 256 + lane; i < 512; i += 32)
        s += dot4(__ldcs(w + i), xs[i]);
    s = warp_reduce(s);
    if (lane == 0) s_gi[kl][gate] = s + b_ih[row];
    __syncthreads();

    if (tid < 4) {
        const int kk = blockIdx.x * 4 + tid;
        float i_r = s_gi[tid][0], i_z = s_gi[tid][1], i_n = s_gi[tid][2];
        float h_r = g_gh[kk], h_z = g_gh[kk + H], h_n = g_gh[kk + 2 * H];
        float rr = 1.f / (1.f + __expf(-(i_r + h_r)));
        float zz = 1.f / (1.f + __expf(-(i_z + h_z)));
        float nn = tanhf(i_n + rr * h_n);
        float h0 = hidden[kk];
        float hn = (1.f - zz) * nn + zz * h0;
        g_hnew[kk]  = hn;
        out[V + kk] = hn;
    }
}

// ---------------------------------------------------------------------------
// K4: logits = out_w @ h_new + out_b. NO register prefetch (occupancy wins:
// 42 regs, occ ~55%, 82.7% DRAM proven). 2 rows per warp interleaved.
// grid = ceil(V/16), block = 256.
// ---------------------------------------------------------------------------
__global__ void __launch_bounds__(256) k4_logits(
    const float* __restrict__ out_w, const float* __restrict__ out_b,
    float* __restrict__ out)
{
    GDC_WAIT();                           // g_hnew from k3
    __shared__ float4 xs[512];
    const int tid  = threadIdx.x;
    const int warp = tid >> 5;
    const int lane = tid & 31;

    for (int i = tid; i < 512; i += 256)
        xs[i] = reinterpret_cast<const float4*>(g_hnew)[i];
    __syncthreads();

    const long long r0 = ((long long)blockIdx.x * 8 + warp) * 2;
    if (r0 >= V) return;
    const bool two = (r0 + 1 < V);

    const float4* w0 = reinterpret_cast<const float4*>(out_w) + r0 * 512;
    const float4* w1 = w0 + (two ? 512 : 0);

    float s0 = 0.f, s1 = 0.f;
    #pragma unroll 8
    for (int i = lane; i < 512; i += 32) {
        float4 b = xs[i];
        s0 += dot4(__ldcs(w0 + i), b);
        s1 += dot4(__ldcs(w1 + i), b);
    }
    s0 = warp_reduce(s0);
    s1 = warp_reduce(s1);
    if (lane == 0) {
        out[r0] = s0 + out_b[r0];
        if (two) out[r0 + 1] = s1 + out_b[r0 + 1];
    }
}

// ---------------------------------------------------------------------------
extern "C" void kernel_launch(void* const* d_in, const int* in_sizes, int n_in,
                              void* d_out, int out_size)
{
    const int*   input_ids = (const int*)  d_in[0];
    const float* hidden    = (const float*)d_in[1];
    const float* enc       = (const float*)d_in[2];
    const float* emb       = (const float*)d_in[3];
    const float* attn_w    = (const float*)d_in[4];
    const float* attn_b    = (const float*)d_in[5];
    const float* comb_w    = (const float*)d_in[6];
    const float* comb_b    = (const float*)d_in[7];
    const float* w_ih      = (const float*)d_in[8];
    const float* w_hh      = (const float*)d_in[9];
    const float* b_ih      = (const float*)d_in[10];
    const float* b_hh      = (const float*)d_in[11];
    const float* out_w     = (const float*)d_in[12];
    const float* out_b     = (const float*)d_in[13];
    float* out = (float*)d_out;

    // First kernel: plain launch (fused scores + softmax + context).
    k1_fused<<<L + 8, 256>>>(input_ids, hidden, emb, attn_w, attn_b, enc, out);

    // Subsequent kernels: programmatic stream serialization (PDL).
    cudaLaunchAttribute attr[1];
    attr[0].id = cudaLaunchAttributeProgrammaticStreamSerialization;
    attr[0].val.programmaticStreamSerializationAllowed = 1;

    {
        cudaLaunchConfig_t cfg = {};
        cfg.gridDim = dim3(1024); cfg.blockDim = dim3(256);
        cfg.attrs = attr; cfg.numAttrs = 1; cfg.stream = 0;
        cudaLaunchKernelEx(&cfg, k2_comb_gh, comb_w, comb_b, w_hh, b_hh, hidden);
    }
    {
        cudaLaunchConfig_t cfg = {};
        cfg.gridDim = dim3(512); cfg.blockDim = dim3(384);
        cfg.attrs = attr; cfg.numAttrs = 1; cfg.stream = 0;
        cudaLaunchKernelEx(&cfg, k3_gru, w_ih, b_ih, hidden, out);
    }
    {
        cudaLaunchConfig_t cfg = {};
        cfg.gridDim = dim3((V + 15) / 16); cfg.blockDim = dim3(256);
        cfg.attrs = attr; cfg.numAttrs = 1; cfg.stream = 0;
        cudaLaunchKernelEx(&cfg, k4_logits, out_w, out_b, out);
    }
}

// round 17
// speedup vs baseline: 1.0328x; 1.0328x over previous
#include <cuda_runtime.h>
#include <math.h>

#define H 2048
#define V 50257
#define L 20

// Programmatic dependent launch controls (sm_90+)
#define GDC_LAUNCH() asm volatile("griddepcontrol.launch_dependents;")
#define GDC_WAIT()   asm volatile("griddepcontrol.wait;" ::: "memory")

// Scratch (device globals: no allocation allowed in kernel_launch)
__device__ __align__(16) float g_sc[L];           // raw attention scores
__device__ __align__(16) float g_concat[2 * H];   // [embedded ; context]
__device__ __align__(16) float g_x[H];            // relu(comb) output
__device__ __align__(16) float g_gh[3 * H];       // w_hh @ h0 + b_hh
__device__ __align__(16) float g_hnew[H];         // new hidden

// Self-resetting sync counters for k1 (return to 0 by end of each launch).
__device__ int c_sc  = 0;     // score blocks done (target 20)
__device__ int c_fin = 0;     // ctx blocks finished (target 8; last one resets)

__device__ __forceinline__ float warp_reduce(float v) {
    #pragma unroll
    for (int o = 16; o > 0; o >>= 1)
        v += __shfl_xor_sync(0xFFFFFFFFu, v, o);
    return v;
}

__device__ __forceinline__ float dot4(float4 a, float4 b) {
    return a.x * b.x + a.y * b.y + a.z * b.z + a.w * b.w;
}

// ---------------------------------------------------------------------------
// K1: fused attention. Blocks 0..19: one score each. Blocks 20..27: softmax
// (redundant) + context + concat (256 j's each), spin on score counter.
// All blocks GDC_LAUNCH at entry -> k2's gh stream starts at k1's START.
// ---------------------------------------------------------------------------
__global__ void __launch_bounds__(256) k1_fused(
    const int* __restrict__ input_ids,
    const float* __restrict__ hidden,
    const float* __restrict__ emb,
    const float* __restrict__ attn_w,
    const float* __restrict__ attn_b,
    const float* __restrict__ enc,
    float* __restrict__ out)
{
    GDC_LAUNCH();
    const int bid = blockIdx.x;
    const int tid = threadIdx.x;
    const int id  = input_ids[0];

    if (bid < L) {
        // ---- score block: s[bid] = attn_w[bid] . [emb_row ; h0] + b ----
        __shared__ float red[8];
        const float4* aw = reinterpret_cast<const float4*>(attn_w + bid * (2 * H));
        const float4* e4 = reinterpret_cast<const float4*>(emb + (long long)id * H);
        const float4* h4 = reinterpret_cast<const float4*>(hidden);

        float s = 0.f;
        #pragma unroll
        for (int i = tid; i < 1024; i += 256) {
            float4 a = __ldcs(aw + i);
            float4 x = (i < 512) ? e4[i] : h4[i - 512];
            s += dot4(a, x);
        }
        s = warp_reduce(s);
        if ((tid & 31) == 0) red[tid >> 5] = s;
        __syncthreads();
        if (tid < 8) {
            float v = red[tid];
            #pragma unroll
            for (int o = 4; o > 0; o >>= 1) v += __shfl_xor_sync(0xFFu, v, o);
            if (tid == 0) {
                g_sc[bid] = v + attn_b[bid];
                __threadfence();
                atomicAdd(&c_sc, 1);
            }
        }
    } else {
        // ---- ctx block: wait for all 20 scores, then context + concat ----
        __shared__ float sw[L];
        if (tid == 0) {
            while (atomicAdd(&c_sc, 0) < L) __nanosleep(64);
        }
        __syncthreads();
        __threadfence();

        if (tid == 0) {
            float m = g_sc[0];
            #pragma unroll
            for (int l = 1; l < L; l++) m = fmaxf(m, g_sc[l]);
            float ssum = 0.f;
            float e[L];
            #pragma unroll
            for (int l = 0; l < L; l++) { e[l] = __expf(g_sc[l] - m); ssum += e[l]; }
            float inv = 1.f / ssum;
            #pragma unroll
            for (int l = 0; l < L; l++) sw[l] = e[l] * inv;
        }
        __syncthreads();

        const int j = (bid - L) * 256 + tid;      // 0..2047
        float ctx = 0.f;
        #pragma unroll
        for (int l = 0; l < L; l++)
            ctx += sw[l] * enc[l * H + j];

        g_concat[j]     = emb[(long long)id * H + j];
        g_concat[H + j] = ctx;

        if (bid == L && tid < L) out[V + H + tid] = sw[tid];

        __syncthreads();
        if (tid == 0) {
            int f = atomicAdd(&c_fin, 1);
            if (f == 7) {                          // last ctx block: reset
                atomicExch(&c_sc, 0);
                atomicExch(&c_fin, 0);
            }
        }
    }
}

// ---------------------------------------------------------------------------
// K2: gh GEMV in blocks 0..767 (NO dependency -> streams from k1's start),
//     comb GEMV in blocks 768..1023 (quarter-row prefetch = 8 float4 keeps
//     whole-kernel regs ~60 so gh blocks keep high occupancy).
// ---------------------------------------------------------------------------
__global__ void __launch_bounds__(256) k2_comb_gh(
    const float* __restrict__ comb_w, const float* __restrict__ comb_b,
    const float* __restrict__ w_hh,   const float* __restrict__ b_hh,
    const float* __restrict__ hidden)
{
    GDC_LAUNCH();
    __shared__ float4 xs[1024];
    const int tid  = threadIdx.x;
    const int warp = tid >> 5;
    const int lane = tid & 31;

    if (blockIdx.x < 768) {
        for (int i = tid; i < 512; i += 256)
            xs[i] = reinterpret_cast<const float4*>(hidden)[i];
        __syncthreads();

        const int r = blockIdx.x * 8 + warp;              // 0..6143
        const float4* w = reinterpret_cast<const float4*>(w_hh) + (long long)r * 512;
        float s = 0.f;
        #pragma unroll 8
        for (int i = lane; i < 512; i += 32)
            s += dot4(__ldcs(w + i), xs[i]);
        s = warp_reduce(s);
        if (lane == 0) g_gh[r] = s + b_hh[r];
    } else {
        const int r = (blockIdx.x - 768) * 8 + warp;      // 0..2047
        const float4* w = reinterpret_cast<const float4*>(comb_w) + (long long)r * 1024;

        float4 wreg[8];
        #pragma unroll
        for (int j = 0; j < 8; j++)
            wreg[j] = __ldcs(w + lane + 32 * j);          // i in [0, 256)

        GDC_WAIT();                                       // g_concat from k1
        for (int i = tid; i < 1024; i += 256)
            xs[i] = reinterpret_cast<const float4*>(g_concat)[i];
        __syncthreads();

        float s = 0.f;
        #pragma unroll
        for (int j = 0; j < 8; j++)
            s += dot4(wreg[j], xs[lane + 32 * j]);
        #pragma unroll 8
        for (int i = 256 + lane; i < 1024; i += 32)
            s += dot4(__ldcs(w + i), xs[i]);
        s = warp_reduce(s);
        if (lane == 0) g_x[r] = fmaxf(s + comb_b[r], 0.f);
    }
}

// ---------------------------------------------------------------------------
// K3: gi GEMV + GRU gates. block = 384 (12 warps = 4 k's x 3 gates),
// grid = 512. Half-row prefetch (8 float4) before the wait.
// ---------------------------------------------------------------------------
__global__ void __launch_bounds__(384) k3_gru(
    const float* __restrict__ w_ih, const float* __restrict__ b_ih,
    const float* __restrict__ hidden, float* __restrict__ out)
{
    GDC_LAUNCH();
    __shared__ float4 xs[512];
    __shared__ float s_gi[4][3];
    const int tid  = threadIdx.x;
    const int warp = tid >> 5;
    const int lane = tid & 31;

    const int kl   = warp / 3;            // 0..3
    const int gate = warp - kl * 3;       // 0..2
    const int k    = blockIdx.x * 4 + kl;
    const int row  = k + gate * H;

    const float4* w = reinterpret_cast<const float4*>(w_ih) + (long long)row * 512;
    float4 wreg[8];
    #pragma unroll
    for (int j = 0; j < 8; j++)
        wreg[j] = __ldcs(w + lane + 32 * j);  // first half of the row

    GDC_WAIT();                           // g_x + g_gh from k2
    for (int i = tid; i < 512; i += 384)
        xs[i] = reinterpret_cast<const float4*>(g_x)[i];
    __syncthreads();

    float s = 0.f;
    #pragma unroll
    for (int j = 0; j < 8; j++)
        s += dot4(wreg[j], xs[lane + 32 * j]);
    #pragma unroll 8
    for (int i = 256 + lane; i < 512; i += 32)
        s += dot4(__ldcs(w + i), xs[i]);
    s = warp_reduce(s);
    if (lane == 0) s_gi[kl][gate] = s + b_ih[row];
    __syncthreads();

    if (tid < 4) {
        const int kk = blockIdx.x * 4 + tid;
        float i_r = s_gi[tid][0], i_z = s_gi[tid][1], i_n = s_gi[tid][2];
        float h_r = g_gh[kk], h_z = g_gh[kk + H], h_n = g_gh[kk + 2 * H];
        float rr = 1.f / (1.f + __expf(-(i_r + h_r)));
        float zz = 1.f / (1.f + __expf(-(i_z + h_z)));
        float nn = tanhf(i_n + rr * h_n);
        float h0 = hidden[kk];
        float hn = (1.f - zz) * nn + zz * h0;
        g_hnew[kk]  = hn;
        out[V + kk] = hn;
    }
}

// ---------------------------------------------------------------------------
// K4: logits = out_w @ h_new + out_b. One row per warp. HALF-ROW register
// prefetch (8 float4, ~60 regs -> ~4 CTAs/SM) before the wait: same machine-
// wide prefetch volume as the full-row version at double the steady-state
// occupancy. Second half streamed from global after the wait.
// grid = ceil(V/8), block = 256.
// ---------------------------------------------------------------------------
__global__ void __launch_bounds__(256) k4_logits(
    const float* __restrict__ out_w, const float* __restrict__ out_b,
    float* __restrict__ out)
{
    __shared__ float4 xs[512];
    const int tid  = threadIdx.x;
    const int warp = tid >> 5;
    const int lane = tid & 31;

    const long long r = (long long)blockIdx.x * 8 + warp;
    const bool valid = (r < V);
    const float4* w = reinterpret_cast<const float4*>(out_w) + r * 512;

    float4 wreg[8];
    if (valid) {
        #pragma unroll
        for (int j = 0; j < 8; j++)
            wreg[j] = __ldcs(w + lane + 32 * j);   // first half of the row
    }

    GDC_WAIT();                           // g_hnew from k3
    for (int i = tid; i < 512; i += 256)
        xs[i] = reinterpret_cast<const float4*>(g_hnew)[i];
    __syncthreads();

    if (!valid) return;
    float s = 0.f;
    #pragma unroll
    for (int j = 0; j < 8; j++)
        s += dot4(wreg[j], xs[lane + 32 * j]);
    #pragma unroll 8
    for (int i = 256 + lane; i < 512; i += 32)
        s += dot4(__ldcs(w + i), xs[i]);
    s = warp_reduce(s);
    if (lane == 0) out[r] = s + out_b[r];
}

// ---------------------------------------------------------------------------
extern "C" void kernel_launch(void* const* d_in, const int* in_sizes, int n_in,
                              void* d_out, int out_size)
{
    const int*   input_ids = (const int*)  d_in[0];
    const float* hidden    = (const float*)d_in[1];
    const float* enc       = (const float*)d_in[2];
    const float* emb       = (const float*)d_in[3];
    const float* attn_w    = (const float*)d_in[4];
    const float* attn_b    = (const float*)d_in[5];
    const float* comb_w    = (const float*)d_in[6];
    const float* comb_b    = (const float*)d_in[7];
    const float* w_ih      = (const float*)d_in[8];
    const float* w_hh      = (const float*)d_in[9];
    const float* b_ih      = (const float*)d_in[10];
    const float* b_hh      = (const float*)d_in[11];
    const float* out_w     = (const float*)d_in[12];
    const float* out_b     = (const float*)d_in[13];
    float* out = (float*)d_out;

    // First kernel: plain launch (fused scores + softmax + context).
    k1_fused<<<L + 8, 256>>>(input_ids, hidden, emb, attn_w, attn_b, enc, out);

    // Subsequent kernels: programmatic stream serialization (PDL).
    cudaLaunchAttribute attr[1];
    attr[0].id = cudaLaunchAttributeProgrammaticStreamSerialization;
    attr[0].val.programmaticStreamSerializationAllowed = 1;

    {
        cudaLaunchConfig_t cfg = {};
        cfg.gridDim = dim3(1024); cfg.blockDim = dim3(256);
        cfg.attrs = attr; cfg.numAttrs = 1; cfg.stream = 0;
        cudaLaunchKernelEx(&cfg, k2_comb_gh, comb_w, comb_b, w_hh, b_hh, hidden);
    }
    {
        cudaLaunchConfig_t cfg = {};
        cfg.gridDim = dim3(512); cfg.blockDim = dim3(384);
        cfg.attrs = attr; cfg.numAttrs = 1; cfg.stream = 0;
        cudaLaunchKernelEx(&cfg, k3_gru, w_ih, b_ih, hidden, out);
    }
    {
        cudaLaunchConfig_t cfg = {};
        cfg.gridDim = dim3((V + 7) / 8); cfg.blockDim = dim3(256);
        cfg.attrs = attr; cfg.numAttrs = 1; cfg.stream = 0;
        cudaLaunchKernelEx(&cfg, k4_logits, out_w, out_b, out);
    }
}